// round 4
// baseline (speedup 1.0000x reference)
#include <cuda_runtime.h>
#include <cuda_fp16.h>
#include <math.h>

#define MAX_NODES 50000
#define MAX_RELS  16
#define D 32

// Scratch (device globals; no allocation allowed)
__device__ __align__(16) __half g_Ph[MAX_NODES * D * 4]; // [n][o][b] halves
__device__ __align__(16) __half g_uh[MAX_NODES * D];     // init_fea @ A_w[0:32]
__device__ __align__(16) __half g_vh[MAX_NODES * D];     // init_fea @ A_w[32:64]
__device__ __align__(16) float  g_agg[MAX_NODES * D];    // curr + scatter of a*msg
__device__ __align__(16) float  g_t[MAX_RELS * D];       // attn_emb @ A_w[64:96] + A_b

struct alignas(8) H4 { __half2 a, b; };

// ---------------------------------------------------------------------------
// K1: node stage. 8 nodes per warp. Block 0 also builds the per-relation
// attention bias table g_t (consumed only by k_edge, which runs after).
// ---------------------------------------------------------------------------
__global__ void __launch_bounds__(256) k_node(
    const float* __restrict__ feat, const float* __restrict__ embed,
    const int* __restrict__ idx, const float* __restrict__ transform,
    const float* __restrict__ weight, const float* __restrict__ A_w,
    const float* __restrict__ selfw, const float* __restrict__ attn_emb,
    const float* __restrict__ A_b, float* __restrict__ out, int n_nodes) {
    __shared__ float sT[64 * 32];      // transform
    __shared__ float sW[4 * 32 * 32];  // basis weights
    __shared__ float sA[64 * 32];      // A_w rows 0..63
    __shared__ float sS[32 * 32];      // self loop

    int tid = threadIdx.x;

    // folded k_rel_t: t[r][o] = A_b[o] + sum_k attn_emb[r,k] * A_w[64+k, o]
    if (blockIdx.x == 0) {
        int r0 = tid >> 5;        // 0..7
        int o = tid & 31;
#pragma unroll
        for (int rr = 0; rr < 2; rr++) {
            int r = r0 + rr * 8;
            float acc = A_b[o];
#pragma unroll
            for (int k = 0; k < 32; k++)
                acc += attn_emb[r * 32 + k] * A_w[(64 + k) * 32 + o];
            g_t[r * 32 + o] = acc;
        }
    }

    for (int i = tid; i < 64 * 32; i += blockDim.x) sT[i] = transform[i];
    for (int i = tid; i < 4 * 32 * 32; i += blockDim.x) sW[i] = weight[i];
    for (int i = tid; i < 64 * 32; i += blockDim.x) sA[i] = A_w[i];
    for (int i = tid; i < 32 * 32; i += blockDim.x) sS[i] = selfw[i];
    __syncthreads();

    int warp = (blockIdx.x * blockDim.x + tid) >> 5;
    int lane = tid & 31;
    int n0 = warp * 8;
    if (n0 >= n_nodes) return;

    float f[8], g[8];
    bool val[8];
#pragma unroll
    for (int j = 0; j < 8; j++) {
        int n = n0 + j;
        val[j] = (n < n_nodes);
        if (val[j]) {
            f[j] = feat[n * 32 + lane];
            g[j] = embed[(long)idx[n] * 32 + lane];
        } else {
            f[j] = 0.f; g[j] = 0.f;
        }
    }

    // Phase A: init_fea (lane = output column)
    float fea[8] = {0.f, 0.f, 0.f, 0.f, 0.f, 0.f, 0.f, 0.f};
#pragma unroll
    for (int k = 0; k < 32; k++) {
        float t1 = sT[k * 32 + lane];
        float t2 = sT[(32 + k) * 32 + lane];
#pragma unroll
        for (int j = 0; j < 8; j++) {
            float fs = __shfl_sync(0xffffffffu, f[j], k);
            float gs = __shfl_sync(0xffffffffu, g[j], k);
            fea[j] += fs * t1 + gs * t2;
        }
    }

    // Phase B: 7 downstream projections of init_fea
    float P0[8] = {0,0,0,0,0,0,0,0}, P1[8] = {0,0,0,0,0,0,0,0};
    float P2[8] = {0,0,0,0,0,0,0,0}, P3[8] = {0,0,0,0,0,0,0,0};
    float u[8] = {0,0,0,0,0,0,0,0}, v[8] = {0,0,0,0,0,0,0,0};
    float c[8] = {0,0,0,0,0,0,0,0};
#pragma unroll
    for (int k = 0; k < 32; k++) {
        float w0 = sW[0 * 1024 + k * 32 + lane];
        float w1 = sW[1 * 1024 + k * 32 + lane];
        float w2 = sW[2 * 1024 + k * 32 + lane];
        float w3 = sW[3 * 1024 + k * 32 + lane];
        float wu = sA[k * 32 + lane];
        float wv = sA[(32 + k) * 32 + lane];
        float wc = sS[k * 32 + lane];
#pragma unroll
        for (int j = 0; j < 8; j++) {
            float s = __shfl_sync(0xffffffffu, fea[j], k);
            P0[j] += s * w0;
            P1[j] += s * w1;
            P2[j] += s * w2;
            P3[j] += s * w3;
            u[j] += s * wu;
            v[j] += s * wv;
            c[j] += s * wc;
        }
    }

#pragma unroll
    for (int j = 0; j < 8; j++) {
        if (!val[j]) continue;
        int n = n0 + j;
        out[(long)n * 64 + lane] = fea[j];                 // out[:,0,:]
        H4 h4;
        h4.a = __halves2half2(__float2half_rn(P0[j]), __float2half_rn(P1[j]));
        h4.b = __halves2half2(__float2half_rn(P2[j]), __float2half_rn(P3[j]));
        *reinterpret_cast<H4*>(&g_Ph[(size_t)n * 128 + lane * 4]) = h4;
        g_uh[n * 32 + lane] = __float2half_rn(u[j]);
        g_vh[n * 32 + lane] = __float2half_rn(v[j]);
        g_agg[n * 32 + lane] = c[j];
    }
}

// ---------------------------------------------------------------------------
// K2: edge stage. 8 edges per warp (two quads, unrolled x2 for MLP);
// 8 lanes per edge; each lane covers 4 output columns.
// ---------------------------------------------------------------------------
__global__ void __launch_bounds__(256) k_edge(
    const int* __restrict__ esrc, const int* __restrict__ edst,
    const int* __restrict__ etype, const float* __restrict__ w_comp,
    const float* __restrict__ B_w, const float* __restrict__ B_b, int n_edges) {
    __shared__ __align__(16) float4 s_wc[MAX_RELS];      // w_comp per rel
    __shared__ __align__(16) float4 s_t4[MAX_RELS * 8];  // attn bias per rel
    __shared__ __align__(16) float4 s_bw4[8];
    __shared__ float s_bb;

    int tid = threadIdx.x;
    if (tid < MAX_RELS)
        s_wc[tid] = reinterpret_cast<const float4*>(w_comp)[tid];
    if (tid < MAX_RELS * 8)
        s_t4[tid] = reinterpret_cast<const float4*>(g_t)[tid];
    if (tid < 8)
        s_bw4[tid] = reinterpret_cast<const float4*>(B_w)[tid];
    if (tid == 0) s_bb = B_b[0];
    __syncthreads();

    int warp = (blockIdx.x * blockDim.x + tid) >> 5;
    int lane = tid & 31;
    int sub = lane >> 3;   // quad slot (0..3)
    int g = lane & 7;      // lane within 8-lane edge group; outputs 4g..4g+3
    float4 bw = s_bw4[g];

    int e[2];
    e[0] = warp * 8 + sub;
    e[1] = e[0] + 4;

    int src[2], dst[2], ty[2];
    bool ok[2];
#pragma unroll
    for (int q = 0; q < 2; q++) {
        ok[q] = (e[q] < n_edges);
        int ee = ok[q] ? e[q] : 0;
        src[q] = esrc[ee];
        dst[q] = edst[ee];
        ty[q] = etype[ee];
    }
    if (!ok[0]) return;

    // Issue all gathers for both edges before consuming (deep MLP)
    uint4 r0[2], r1[2];
    uint2 uu[2], vv[2];
#pragma unroll
    for (int q = 0; q < 2; q++) {
        const uint4* Pp =
            reinterpret_cast<const uint4*>(g_Ph + (size_t)src[q] * 128 + g * 16);
        r0[q] = Pp[0];
        r1[q] = Pp[1];
        uu[q] = *reinterpret_cast<const uint2*>(g_uh + (size_t)src[q] * 32 + g * 4);
        vv[q] = *reinterpret_cast<const uint2*>(g_vh + (size_t)dst[q] * 32 + g * 4);
    }

#pragma unroll
    for (int q = 0; q < 2; q++) {
        if (!ok[q]) break;
        float4 cc = s_wc[ty[q]];
        float4 t4 = s_t4[ty[q] * 8 + g];

        float2 p00 = __half22float2(*reinterpret_cast<__half2*>(&r0[q].x));
        float2 p01 = __half22float2(*reinterpret_cast<__half2*>(&r0[q].y));
        float2 p10 = __half22float2(*reinterpret_cast<__half2*>(&r0[q].z));
        float2 p11 = __half22float2(*reinterpret_cast<__half2*>(&r0[q].w));
        float2 p20 = __half22float2(*reinterpret_cast<__half2*>(&r1[q].x));
        float2 p21 = __half22float2(*reinterpret_cast<__half2*>(&r1[q].y));
        float2 p30 = __half22float2(*reinterpret_cast<__half2*>(&r1[q].z));
        float2 p31 = __half22float2(*reinterpret_cast<__half2*>(&r1[q].w));

        float4 msg;
        msg.x = p00.x * cc.x + p00.y * cc.y + p01.x * cc.z + p01.y * cc.w;
        msg.y = p10.x * cc.x + p10.y * cc.y + p11.x * cc.z + p11.y * cc.w;
        msg.z = p20.x * cc.x + p20.y * cc.y + p21.x * cc.z + p21.y * cc.w;
        msg.w = p30.x * cc.x + p30.y * cc.y + p31.x * cc.z + p31.y * cc.w;

        float2 u0 = __half22float2(*reinterpret_cast<__half2*>(&uu[q].x));
        float2 u1 = __half22float2(*reinterpret_cast<__half2*>(&uu[q].y));
        float2 v0 = __half22float2(*reinterpret_cast<__half2*>(&vv[q].x));
        float2 v1 = __half22float2(*reinterpret_cast<__half2*>(&vv[q].y));

        float zx = fmaxf(u0.x + v0.x + t4.x, 0.f);
        float zy = fmaxf(u0.y + v0.y + t4.y, 0.f);
        float zz = fmaxf(u1.x + v1.x + t4.z, 0.f);
        float zw = fmaxf(u1.y + v1.y + t4.w, 0.f);

        float s = zx * bw.x + zy * bw.y + zz * bw.z + zw * bw.w;
        // reduce within 8-lane group (xor offsets 4,2,1 stay inside group)
        s += __shfl_xor_sync(0xffffffffu, s, 4);
        s += __shfl_xor_sync(0xffffffffu, s, 2);
        s += __shfl_xor_sync(0xffffffffu, s, 1);
        float a = 1.f / (1.f + __expf(-(s + s_bb)));

        float4 r = make_float4(a * msg.x, a * msg.y, a * msg.z, a * msg.w);
        atomicAdd(reinterpret_cast<float4*>(g_agg) + (size_t)dst[q] * 8 + g, r);
    }
}

// ---------------------------------------------------------------------------
// K3: h = relu(agg) -> out[:,1,:]  (float4 vectorized)
// ---------------------------------------------------------------------------
__global__ void k_final(float* __restrict__ out, int n4) {
    int i = blockIdx.x * blockDim.x + threadIdx.x;   // over n_nodes*8 float4s
    if (i >= n4) return;
    int n = i >> 3;
    int q = i & 7;
    float4 v = reinterpret_cast<const float4*>(g_agg)[i];
    float4 r = make_float4(fmaxf(v.x, 0.f), fmaxf(v.y, 0.f),
                           fmaxf(v.z, 0.f), fmaxf(v.w, 0.f));
    reinterpret_cast<float4*>(out)[(size_t)n * 16 + 8 + q] = r;
}

extern "C" void kernel_launch(void* const* d_in, const int* in_sizes, int n_in,
                              void* d_out, int out_size) {
    const float* feat      = (const float*)d_in[0];
    const float* embed     = (const float*)d_in[1];
    const float* transform = (const float*)d_in[2];
    const float* weight    = (const float*)d_in[3];
    const float* w_comp    = (const float*)d_in[4];
    const float* selfw     = (const float*)d_in[5];
    const float* A_w       = (const float*)d_in[6];
    const float* A_b       = (const float*)d_in[7];
    const float* B_w       = (const float*)d_in[8];
    const float* B_b       = (const float*)d_in[9];
    const float* attn_emb  = (const float*)d_in[10];
    const int*   idx       = (const int*)d_in[11];
    const int*   esrc      = (const int*)d_in[12];
    const int*   edst      = (const int*)d_in[13];
    const int*   ety       = (const int*)d_in[14];
    float* out = (float*)d_out;

    int n_nodes = in_sizes[0] / 32;
    int n_edges = in_sizes[12];

    int warps1 = (n_nodes + 7) / 8;
    int blocks1 = (warps1 * 32 + 255) / 256;
    k_node<<<blocks1, 256>>>(feat, embed, idx, transform, weight, A_w, selfw,
                             attn_emb, A_b, out, n_nodes);

    int blocks2 = (n_edges + 63) / 64;  // 8 warps/block, 8 edges/warp
    k_edge<<<blocks2, 256>>>(esrc, edst, ety, w_comp, B_w, B_b, n_edges);

    int n4 = n_nodes * 8;
    int blocks3 = (n4 + 255) / 256;
    k_final<<<blocks3, 256>>>(out, n4);
}

// round 5
// speedup vs baseline: 1.1716x; 1.1716x over previous
#include <cuda_runtime.h>
#include <cuda_fp16.h>
#include <math.h>

#define MAX_NODES 50000
#define MAX_RELS  16
#define D 32

// Scratch (device globals; no allocation allowed)
__device__ __align__(16) __half g_Ph[MAX_NODES * D * 4]; // [n][o][b] halves
__device__ __align__(16) __half g_uh[MAX_NODES * D];     // init_fea @ A_w[0:32]
__device__ __align__(16) __half g_vh[MAX_NODES * D];     // init_fea @ A_w[32:64]
__device__ __align__(16) float  g_agg[MAX_NODES * D];    // curr + scatter of a*msg
__device__ __align__(16) float  g_t[MAX_RELS * D];       // attn_emb @ A_w[64:96] + A_b

struct alignas(8) H4 { __half2 a, b; };

// ---------------------------------------------------------------------------
// K1: node stage. 4 nodes per warp, persistent grid-stride over node chunks.
// Block 0 also builds the per-relation attention bias table g_t.
// ---------------------------------------------------------------------------
__global__ void __launch_bounds__(256) k_node(
    const float* __restrict__ feat, const float* __restrict__ embed,
    const int* __restrict__ idx, const float* __restrict__ transform,
    const float* __restrict__ weight, const float* __restrict__ A_w,
    const float* __restrict__ selfw, const float* __restrict__ attn_emb,
    const float* __restrict__ A_b, float* __restrict__ out, int n_nodes) {
    __shared__ float sT[64 * 32];      // transform
    __shared__ float sW[4 * 32 * 32];  // basis weights
    __shared__ float sA[64 * 32];      // A_w rows 0..63
    __shared__ float sS[32 * 32];      // self loop

    int tid = threadIdx.x;

    // folded k_rel_t: t[r][o] = A_b[o] + sum_k attn_emb[r,k] * A_w[64+k, o]
    if (blockIdx.x == 0) {
        int r0 = tid >> 5;        // 0..7
        int o = tid & 31;
#pragma unroll
        for (int rr = 0; rr < 2; rr++) {
            int r = r0 + rr * 8;
            float acc = A_b[o];
#pragma unroll
            for (int k = 0; k < 32; k++)
                acc += attn_emb[r * 32 + k] * A_w[(64 + k) * 32 + o];
            g_t[r * 32 + o] = acc;
        }
    }

    for (int i = tid; i < 64 * 32; i += blockDim.x) sT[i] = transform[i];
    for (int i = tid; i < 4 * 32 * 32; i += blockDim.x) sW[i] = weight[i];
    for (int i = tid; i < 64 * 32; i += blockDim.x) sA[i] = A_w[i];
    for (int i = tid; i < 32 * 32; i += blockDim.x) sS[i] = selfw[i];
    __syncthreads();

    int lane = tid & 31;
    int warp_local = tid >> 5;                        // 0..7
    int warps_per_grid = gridDim.x * (blockDim.x >> 5);
    int warp0 = blockIdx.x * (blockDim.x >> 5) + warp_local;
    int n_tasks = (n_nodes + 3) >> 2;                 // warp-tasks of 4 nodes

    for (int task = warp0; task < n_tasks; task += warps_per_grid) {
        int n0 = task * 4;

        float f[4], g[4];
        bool val[4];
#pragma unroll
        for (int j = 0; j < 4; j++) {
            int n = n0 + j;
            val[j] = (n < n_nodes);
            if (val[j]) {
                f[j] = feat[n * 32 + lane];
                g[j] = embed[(long)idx[n] * 32 + lane];
            } else {
                f[j] = 0.f; g[j] = 0.f;
            }
        }

        // Phase A: init_fea (lane = output column)
        float fea[4] = {0.f, 0.f, 0.f, 0.f};
#pragma unroll
        for (int k = 0; k < 32; k++) {
            float t1 = sT[k * 32 + lane];
            float t2 = sT[(32 + k) * 32 + lane];
#pragma unroll
            for (int j = 0; j < 4; j++) {
                float fs = __shfl_sync(0xffffffffu, f[j], k);
                float gs = __shfl_sync(0xffffffffu, g[j], k);
                fea[j] += fs * t1 + gs * t2;
            }
        }

        // Phase B: 7 downstream projections of init_fea
        float P0[4] = {0,0,0,0}, P1[4] = {0,0,0,0};
        float P2[4] = {0,0,0,0}, P3[4] = {0,0,0,0};
        float u[4] = {0,0,0,0}, v[4] = {0,0,0,0}, c[4] = {0,0,0,0};
#pragma unroll
        for (int k = 0; k < 32; k++) {
            float w0 = sW[0 * 1024 + k * 32 + lane];
            float w1 = sW[1 * 1024 + k * 32 + lane];
            float w2 = sW[2 * 1024 + k * 32 + lane];
            float w3 = sW[3 * 1024 + k * 32 + lane];
            float wu = sA[k * 32 + lane];
            float wv = sA[(32 + k) * 32 + lane];
            float wc = sS[k * 32 + lane];
#pragma unroll
            for (int j = 0; j < 4; j++) {
                float s = __shfl_sync(0xffffffffu, fea[j], k);
                P0[j] += s * w0;
                P1[j] += s * w1;
                P2[j] += s * w2;
                P3[j] += s * w3;
                u[j] += s * wu;
                v[j] += s * wv;
                c[j] += s * wc;
            }
        }

#pragma unroll
        for (int j = 0; j < 4; j++) {
            if (!val[j]) continue;
            int n = n0 + j;
            out[(long)n * 64 + lane] = fea[j];             // out[:,0,:]
            H4 h4;
            h4.a = __halves2half2(__float2half_rn(P0[j]), __float2half_rn(P1[j]));
            h4.b = __halves2half2(__float2half_rn(P2[j]), __float2half_rn(P3[j]));
            *reinterpret_cast<H4*>(&g_Ph[(size_t)n * 128 + lane * 4]) = h4;
            g_uh[n * 32 + lane] = __float2half_rn(u[j]);
            g_vh[n * 32 + lane] = __float2half_rn(v[j]);
            g_agg[n * 32 + lane] = c[j];
        }
    }
}

// ---------------------------------------------------------------------------
// K2: edge stage. 8 edges per warp (two quads, unrolled x2 for MLP);
// 8 lanes per edge; each lane covers 4 output columns.
// ---------------------------------------------------------------------------
__global__ void __launch_bounds__(256) k_edge(
    const int* __restrict__ esrc, const int* __restrict__ edst,
    const int* __restrict__ etype, const float* __restrict__ w_comp,
    const float* __restrict__ B_w, const float* __restrict__ B_b, int n_edges) {
    __shared__ __align__(16) float4 s_wc[MAX_RELS];      // w_comp per rel
    __shared__ __align__(16) float4 s_t4[MAX_RELS * 8];  // attn bias per rel
    __shared__ __align__(16) float4 s_bw4[8];
    __shared__ float s_bb;

    int tid = threadIdx.x;
    if (tid < MAX_RELS)
        s_wc[tid] = reinterpret_cast<const float4*>(w_comp)[tid];
    if (tid < MAX_RELS * 8)
        s_t4[tid] = reinterpret_cast<const float4*>(g_t)[tid];
    if (tid < 8)
        s_bw4[tid] = reinterpret_cast<const float4*>(B_w)[tid];
    if (tid == 0) s_bb = B_b[0];
    __syncthreads();

    int warp = (blockIdx.x * blockDim.x + tid) >> 5;
    int lane = tid & 31;
    int sub = lane >> 3;   // quad slot (0..3)
    int g = lane & 7;      // lane within 8-lane edge group; outputs 4g..4g+3
    float4 bw = s_bw4[g];

    int e[2];
    e[0] = warp * 8 + sub;
    e[1] = e[0] + 4;

    int src[2], dst[2], ty[2];
    bool ok[2];
#pragma unroll
    for (int q = 0; q < 2; q++) {
        ok[q] = (e[q] < n_edges);
        int ee = ok[q] ? e[q] : 0;
        src[q] = esrc[ee];
        dst[q] = edst[ee];
        ty[q] = etype[ee];
    }
    if (!ok[0]) return;

    // Issue all gathers for both edges before consuming (deep MLP)
    uint4 r0[2], r1[2];
    uint2 uu[2], vv[2];
#pragma unroll
    for (int q = 0; q < 2; q++) {
        const uint4* Pp =
            reinterpret_cast<const uint4*>(g_Ph + (size_t)src[q] * 128 + g * 16);
        r0[q] = Pp[0];
        r1[q] = Pp[1];
        uu[q] = *reinterpret_cast<const uint2*>(g_uh + (size_t)src[q] * 32 + g * 4);
        vv[q] = *reinterpret_cast<const uint2*>(g_vh + (size_t)dst[q] * 32 + g * 4);
    }

#pragma unroll
    for (int q = 0; q < 2; q++) {
        if (!ok[q]) break;
        float4 cc = s_wc[ty[q]];
        float4 t4 = s_t4[ty[q] * 8 + g];

        float2 p00 = __half22float2(*reinterpret_cast<__half2*>(&r0[q].x));
        float2 p01 = __half22float2(*reinterpret_cast<__half2*>(&r0[q].y));
        float2 p10 = __half22float2(*reinterpret_cast<__half2*>(&r0[q].z));
        float2 p11 = __half22float2(*reinterpret_cast<__half2*>(&r0[q].w));
        float2 p20 = __half22float2(*reinterpret_cast<__half2*>(&r1[q].x));
        float2 p21 = __half22float2(*reinterpret_cast<__half2*>(&r1[q].y));
        float2 p30 = __half22float2(*reinterpret_cast<__half2*>(&r1[q].z));
        float2 p31 = __half22float2(*reinterpret_cast<__half2*>(&r1[q].w));

        float4 msg;
        msg.x = p00.x * cc.x + p00.y * cc.y + p01.x * cc.z + p01.y * cc.w;
        msg.y = p10.x * cc.x + p10.y * cc.y + p11.x * cc.z + p11.y * cc.w;
        msg.z = p20.x * cc.x + p20.y * cc.y + p21.x * cc.z + p21.y * cc.w;
        msg.w = p30.x * cc.x + p30.y * cc.y + p31.x * cc.z + p31.y * cc.w;

        float2 u0 = __half22float2(*reinterpret_cast<__half2*>(&uu[q].x));
        float2 u1 = __half22float2(*reinterpret_cast<__half2*>(&uu[q].y));
        float2 v0 = __half22float2(*reinterpret_cast<__half2*>(&vv[q].x));
        float2 v1 = __half22float2(*reinterpret_cast<__half2*>(&vv[q].y));

        float zx = fmaxf(u0.x + v0.x + t4.x, 0.f);
        float zy = fmaxf(u0.y + v0.y + t4.y, 0.f);
        float zz = fmaxf(u1.x + v1.x + t4.z, 0.f);
        float zw = fmaxf(u1.y + v1.y + t4.w, 0.f);

        float s = zx * bw.x + zy * bw.y + zz * bw.z + zw * bw.w;
        // reduce within 8-lane group (xor offsets 4,2,1 stay inside group)
        s += __shfl_xor_sync(0xffffffffu, s, 4);
        s += __shfl_xor_sync(0xffffffffu, s, 2);
        s += __shfl_xor_sync(0xffffffffu, s, 1);
        float a = 1.f / (1.f + __expf(-(s + s_bb)));

        float4 r = make_float4(a * msg.x, a * msg.y, a * msg.z, a * msg.w);
        atomicAdd(reinterpret_cast<float4*>(g_agg) + (size_t)dst[q] * 8 + g, r);
    }
}

// ---------------------------------------------------------------------------
// K3: h = relu(agg) -> out[:,1,:]  (float4 vectorized)
// ---------------------------------------------------------------------------
__global__ void k_final(float* __restrict__ out, int n4) {
    int i = blockIdx.x * blockDim.x + threadIdx.x;   // over n_nodes*8 float4s
    if (i >= n4) return;
    int n = i >> 3;
    int q = i & 7;
    float4 v = reinterpret_cast<const float4*>(g_agg)[i];
    float4 r = make_float4(fmaxf(v.x, 0.f), fmaxf(v.y, 0.f),
                           fmaxf(v.z, 0.f), fmaxf(v.w, 0.f));
    reinterpret_cast<float4*>(out)[(size_t)n * 16 + 8 + q] = r;
}

extern "C" void kernel_launch(void* const* d_in, const int* in_sizes, int n_in,
                              void* d_out, int out_size) {
    const float* feat      = (const float*)d_in[0];
    const float* embed     = (const float*)d_in[1];
    const float* transform = (const float*)d_in[2];
    const float* weight    = (const float*)d_in[3];
    const float* w_comp    = (const float*)d_in[4];
    const float* selfw     = (const float*)d_in[5];
    const float* A_w       = (const float*)d_in[6];
    const float* A_b       = (const float*)d_in[7];
    const float* B_w       = (const float*)d_in[8];
    const float* B_b       = (const float*)d_in[9];
    const float* attn_emb  = (const float*)d_in[10];
    const int*   idx       = (const int*)d_in[11];
    const int*   esrc      = (const int*)d_in[12];
    const int*   edst      = (const int*)d_in[13];
    const int*   ety       = (const int*)d_in[14];
    float* out = (float*)d_out;

    int n_nodes = in_sizes[0] / 32;
    int n_edges = in_sizes[12];

    // Persistent node kernel: ~3 blocks/SM (57KB smem each)
    int blocks1 = 444;
    k_node<<<blocks1, 256>>>(feat, embed, idx, transform, weight, A_w, selfw,
                             attn_emb, A_b, out, n_nodes);

    int blocks2 = (n_edges + 63) / 64;  // 8 warps/block, 8 edges/warp
    k_edge<<<blocks2, 256>>>(esrc, edst, ety, w_comp, B_w, B_b, n_edges);

    int n4 = n_nodes * 8;
    int blocks3 = (n4 + 255) / 256;
    k_final<<<blocks3, 256>>>(out, n4);
}